// round 14
// baseline (speedup 1.0000x reference)
#include <cuda_runtime.h>
#include <cstdint>

#define TT 1024
#define BB 512
#define HH 15
#define II 10
#define OO 128
#define RING 32          // h-row ring depth per batch (power of 2)
#define PUB 8            // producer publishes every PUB steps
#define GUARD 16         // producer checks consumers every GUARD steps

typedef unsigned long long ull;

__device__ __forceinline__ ull pk(float lo, float hi) {
    ull r; asm("mov.b64 %0, {%1, %2};" : "=l"(r) : "f"(lo), "f"(hi)); return r;
}
__device__ __forceinline__ void upk(ull v, float& lo, float& hi) {
    asm("mov.b64 {%0, %1}, %2;" : "=f"(lo), "=f"(hi) : "l"(v));
}
__device__ __forceinline__ ull fma2(ull a, ull b, ull c) {
    ull d; asm("fma.rn.f32x2 %0, %1, %2, %3;" : "=l"(d) : "l"(a), "l"(b), "l"(c)); return d;
}
__device__ __forceinline__ ull add2(ull a, ull b) {
    ull d; asm("add.rn.f32x2 %0, %1, %2;" : "=l"(d) : "l"(a), "l"(b)); return d;
}
__device__ __forceinline__ float ftanh_mufu(float x) {
    float r; asm("tanh.approx.f32 %0, %1;" : "=f"(r) : "f"(x)); return r;
}
// Accurate sigmoid (output layer; not on the recurrence critical path)
__device__ __forceinline__ float fsig(float x) {
    float e; asm("ex2.approx.f32 %0, %1;" : "=f"(e) : "f"(-1.4426950408889634f * x));
    float d = e + 1.0f;
    float r; asm("rcp.approx.f32 %0, %1;" : "=f"(r) : "f"(d));
    return r;
}

__device__ __forceinline__ uint32_t smem_u32(const void* p) {
    uint32_t a;
    asm("{ .reg .u64 t; cvta.to.shared.u64 t, %1; cvt.u32.u64 %0, t; }" : "=r"(a) : "l"(p));
    return a;
}
__device__ __forceinline__ void sts_f32(uint32_t addr, float v) {
    asm volatile("st.shared.f32 [%0], %1;" :: "r"(addr), "f"(v) : "memory");
}
__device__ __forceinline__ void lds_v2u64(uint32_t addr, ull& a, ull& b) {
    asm volatile("ld.shared.v2.u64 {%0, %1}, [%2];" : "=l"(a), "=l"(b) : "r"(addr) : "memory");
}
__device__ __forceinline__ void st_release_s32(uint32_t addr, int v) {
    asm volatile("st.release.cta.shared.u32 [%0], %1;" :: "r"(addr), "r"(v) : "memory");
}
__device__ __forceinline__ int ld_acquire_s32(uint32_t addr) {
    int v; asm volatile("ld.acquire.cta.shared.u32 %0, [%1];" : "=r"(v) : "r"(addr) : "memory");
    return v;
}

// ---------------------------------------------------------------------------
// Fused persistent kernel. Block = 10 warps (320 threads):
//   warps 8..9 : GRU recurrence producers, TWO batches per warp interleaved
//                (latency hiding: W_hh regs shared, chains independent)
//   warps 0..7 : output projection consumers, two per batch, parity-split
//                over t (half=0 even t, half=1 odd t)
// Hidden rows flow through 32-deep smem rings with release/acquire counters.
// ---------------------------------------------------------------------------
__global__ void __launch_bounds__(320, 1) gru_fused(
    const float* __restrict__ feed, const float* __restrict__ h0,
    const float* __restrict__ W_ih, const float* __restrict__ W_hh,
    const float* __restrict__ b_ih, const float* __restrict__ b_hh,
    const float* __restrict__ W_out, const float* __restrict__ b_out,
    float* __restrict__ out)
{
    __shared__ __align__(16) float hring[4][RING][16];   // 8 KB
    __shared__ int prod[4];
    __shared__ int cons[4][2];

    const int tid  = threadIdx.x;
    const int wid  = tid >> 5;
    const int lane = tid & 31;

    // zero ring (column 15 of every slot must stay 0 forever) + counters
    for (int i = tid; i < 4 * RING * 16; i += 320)
        (&hring[0][0][0])[i] = 0.0f;
    if (tid < 4) prod[tid] = 0;
    if (tid < 8) cons[tid >> 1][tid & 1] = 0;
    __syncthreads();

    if (wid >= 8) {
        // ============ producer: 2 interleaved recurrences per warp ============
        const int pw  = wid - 8;                  // 0 or 1
        const int blA = 2 * pw;                   // batch slots
        const int blB = 2 * pw + 1;
        const int bA  = blockIdx.x * 4 + blA;
        const int bB  = blockIdx.x * 4 + blB;

        const uint32_t ringA = smem_u32(&hring[blA][0][0]);
        const uint32_t ringB = smem_u32(&hring[blB][0][0]);
        const uint32_t prodA = smem_u32(&prod[blA]);
        const uint32_t prodB = smem_u32(&prod[blB]);
        const uint32_t cA0 = smem_u32(&cons[blA][0]);
        const uint32_t cA1 = smem_u32(&cons[blA][1]);
        const uint32_t cB0 = smem_u32(&cons[blB][0]);
        const uint32_t cB1 = smem_u32(&cons[blB][1]);

        const int j = (lane < HH) ? lane : 0;     // inactive lanes shadow unit 0

        // W_hh rows j (r), 15+j (z) scaled 0.5 ; 30+j (n) unscaled — SHARED A/B
        ull wr[8], wz[8], wn[8];
#pragma unroll
        for (int i = 0; i < 8; i++) {
            const int k0 = 2 * i, k1 = 2 * i + 1;
            float r0 = W_hh[j * HH + k0]            * 0.5f;
            float z0 = W_hh[(HH + j) * HH + k0]     * 0.5f;
            float n0 = W_hh[(2 * HH + j) * HH + k0];
            float r1 = (k1 < HH) ? W_hh[j * HH + k1]            * 0.5f : 0.0f;
            float z1 = (k1 < HH) ? W_hh[(HH + j) * HH + k1]     * 0.5f : 0.0f;
            float n1 = (k1 < HH) ? W_hh[(2 * HH + j) * HH + k1]        : 0.0f;
            wr[i] = pk(r0, r1); wz[i] = pk(z0, z1); wn[i] = pk(n0, n1);
        }

        // per-batch gate constants
        float crA = b_ih[j] + b_hh[j],            crB = crA;
        float czA = b_ih[HH + j] + b_hh[HH + j],  czB = czA;
        float cnA = b_ih[2 * HH + j],             cnB = cnA;
        const float bn = b_hh[2 * HH + j];
#pragma unroll
        for (int k = 0; k < II; k++) {
            float xA = feed[bA * II + k];
            float xB = feed[bB * II + k];
            float wih_r = W_ih[j * II + k];
            float wih_z = W_ih[(HH + j) * II + k];
            float wih_n = W_ih[(2 * HH + j) * II + k];
            crA = fmaf(xA, wih_r, crA);  crB = fmaf(xB, wih_r, crB);
            czA = fmaf(xA, wih_z, czA);  czB = fmaf(xB, wih_z, czB);
            cnA = fmaf(xA, wih_n, cnA);  cnB = fmaf(xB, wih_n, cnB);
        }
        crA *= 0.5f; czA *= 0.5f;
        crB *= 0.5f; czB *= 0.5f;

        float hA = (lane < HH) ? h0[bA * HH + j] : 0.0f;
        float hB = (lane < HH) ? h0[bB * HH + j] : 0.0f;

        const ull crpA = pk(crA, 0.0f), crpB = pk(crB, 0.0f);
        const ull czpA = pk(czA, 0.0f), czpB = pk(czB, 0.0f);
        const ull bnp  = pk(bn, 0.0f);

        // prime both: publish initial h into scratch slot RING-1, reload packed
        {
            uint32_t saA = ringA + (uint32_t)((RING - 1) * 64);
            uint32_t saB = ringB + (uint32_t)((RING - 1) * 64);
            if (lane < HH) { sts_f32(saA + (uint32_t)lane * 4, hA);
                             sts_f32(saB + (uint32_t)lane * 4, hB); }
            __syncwarp();
        }
        ull hpA[8], hpB[8];
        {
            uint32_t saA = ringA + (uint32_t)((RING - 1) * 64);
            uint32_t saB = ringB + (uint32_t)((RING - 1) * 64);
            lds_v2u64(saA,      hpA[0], hpA[1]);
            lds_v2u64(saA + 16, hpA[2], hpA[3]);
            lds_v2u64(saA + 32, hpA[4], hpA[5]);
            lds_v2u64(saA + 48, hpA[6], hpA[7]);
            lds_v2u64(saB,      hpB[0], hpB[1]);
            lds_v2u64(saB + 16, hpB[2], hpB[3]);
            lds_v2u64(saB + 32, hpB[4], hpB[5]);
            lds_v2u64(saB + 48, hpB[6], hpB[7]);
        }

        for (int t0 = 0; t0 < TT; t0 += PUB) {
            // overrun guard at chunk boundary: both batches' parity consumers
            if ((t0 & (GUARD - 1)) == 0) {
                for (;;) {
                    int c0 = ld_acquire_s32(cA0);
                    int c1 = ld_acquire_s32(cA1);
                    int c2 = ld_acquire_s32(cB0);
                    int c3 = ld_acquire_s32(cB1);
                    int cm = c0 < c1 ? c0 : c1;
                    cm = cm < c2 ? cm : c2;
                    cm = cm < c3 ? cm : c3;
                    if (t0 - cm <= (RING - GUARD)) break;
                    __nanosleep(32);
                }
            }
#pragma unroll
            for (int tt = 0; tt < PUB; tt++) {
                const int t = t0 + tt;
                // ---- gate dots, both batches (12 independent f32x2 chains) ----
                ull arA0 = crpA, azA0 = czpA, anA0 = bnp;
                ull arA1 = 0ULL, azA1 = 0ULL, anA1 = 0ULL;
                ull arB0 = crpB, azB0 = czpB, anB0 = bnp;
                ull arB1 = 0ULL, azB1 = 0ULL, anB1 = 0ULL;
#pragma unroll
                for (int i = 0; i < 4; i++) {
                    arA0 = fma2(wr[i], hpA[i], arA0);
                    azA0 = fma2(wz[i], hpA[i], azA0);
                    anA0 = fma2(wn[i], hpA[i], anA0);
                    arB0 = fma2(wr[i], hpB[i], arB0);
                    azB0 = fma2(wz[i], hpB[i], azB0);
                    anB0 = fma2(wn[i], hpB[i], anB0);
                }
#pragma unroll
                for (int i = 4; i < 8; i++) {
                    arA1 = fma2(wr[i], hpA[i], arA1);
                    azA1 = fma2(wz[i], hpA[i], azA1);
                    anA1 = fma2(wn[i], hpA[i], anA1);
                    arB1 = fma2(wr[i], hpB[i], arB1);
                    azB1 = fma2(wz[i], hpB[i], azB1);
                    anB1 = fma2(wn[i], hpB[i], anB1);
                }
                float l, hvv;
                float grA, gzA, gnA, grB, gzB, gnB;
                upk(add2(arA0, arA1), l, hvv); grA = l + hvv;
                upk(add2(azA0, azA1), l, hvv); gzA = l + hvv;
                upk(add2(anA0, anA1), l, hvv); gnA = l + hvv;
                upk(add2(arB0, arB1), l, hvv); grB = l + hvv;
                upk(add2(azB0, azB1), l, hvv); gzB = l + hvv;
                upk(add2(anB0, anB1), l, hvv); gnB = l + hvv;

                // ---- activations + updates, both batches ----
                const float trA  = ftanh_mufu(grA);
                const float trB  = ftanh_mufu(grB);
                const float tzA  = ftanh_mufu(gzA);
                const float tzB  = ftanh_mufu(gzB);
                const float rA   = fmaf(0.5f, trA, 0.5f);
                const float rB   = fmaf(0.5f, trB, 0.5f);
                const float omzA = fmaf(-0.5f, tzA, 0.5f);
                const float omzB = fmaf(-0.5f, tzB, 0.5f);
                const float zA   = fmaf(0.5f, tzA, 0.5f);
                const float zB   = fmaf(0.5f, tzB, 0.5f);
                const float zhA  = zA * hA;
                const float zhB  = zB * hB;
                const float nA   = ftanh_mufu(fmaf(rA, gnA, cnA));
                const float nB   = ftanh_mufu(fmaf(rB, gnB, cnB));
                hA = fmaf(omzA, nA, zhA);
                hB = fmaf(omzB, nB, zhB);

                // ---- publish + reload, both batches ----
                const uint32_t saA = ringA + (uint32_t)((t & (RING - 1)) * 64);
                const uint32_t saB = ringB + (uint32_t)((t & (RING - 1)) * 64);
                if (lane < HH) { sts_f32(saA + (uint32_t)lane * 4, hA);
                                 sts_f32(saB + (uint32_t)lane * 4, hB); }
                __syncwarp();
                lds_v2u64(saA,      hpA[0], hpA[1]);
                lds_v2u64(saA + 16, hpA[2], hpA[3]);
                lds_v2u64(saA + 32, hpA[4], hpA[5]);
                lds_v2u64(saA + 48, hpA[6], hpA[7]);
                lds_v2u64(saB,      hpB[0], hpB[1]);
                lds_v2u64(saB + 16, hpB[2], hpB[3]);
                lds_v2u64(saB + 32, hpB[4], hpB[5]);
                lds_v2u64(saB + 48, hpB[6], hpB[7]);
            }
            // amortized release for both batches
            if (lane == 0) { st_release_s32(prodA, t0 + PUB);
                             st_release_s32(prodB, t0 + PUB); }
        }
    } else {
        // ================= consumer: output projection =================
        // two warps per batch, parity-split over t
        const int bl   = wid & 3;
        const int half = wid >> 2;                 // 0: even t, 1: odd t
        const int b    = blockIdx.x * 4 + bl;
        const uint32_t ring_a = smem_u32(&hring[bl][0][0]);
        const uint32_t prod_a = smem_u32(&prod[bl]);
        const uint32_t cons_a = smem_u32(&cons[bl][half]);

        const int o0 = lane * 4;
        ull wv[4][8];
        ull bo2[4];
#pragma unroll
        for (int oo = 0; oo < 4; oo++) {
            bo2[oo] = pk(b_out[o0 + oo], 0.0f);
#pragma unroll
            for (int i = 0; i < 8; i++) {
                const int k0 = 2 * i, k1 = 2 * i + 1;
                float w0 = W_out[(o0 + oo) * HH + k0];
                float w1 = (k1 < HH) ? W_out[(o0 + oo) * HH + k1] : 0.0f;
                wv[oo][i] = pk(w0, w1);
            }
        }

        float* op = out + (size_t)(half) * BB * OO + (size_t)b * OO + o0;

        for (int t = half; t < TT; t += 2) {
            // throttled spin; producer publishes in chunks of PUB
            while (ld_acquire_s32(prod_a) <= t) { __nanosleep(32); }

            uint32_t sa = ring_a + (uint32_t)((t & (RING - 1)) * 64);
            ull hp[8];
            lds_v2u64(sa,      hp[0], hp[1]);
            lds_v2u64(sa + 16, hp[2], hp[3]);
            lds_v2u64(sa + 32, hp[4], hp[5]);
            lds_v2u64(sa + 48, hp[6], hp[7]);

            ull acc0 = bo2[0], acc1 = bo2[1], acc2 = bo2[2], acc3 = bo2[3];
#pragma unroll
            for (int i = 0; i < 8; i++) {       // 4 independent chains
                acc0 = fma2(wv[0][i], hp[i], acc0);
                acc1 = fma2(wv[1][i], hp[i], acc1);
                acc2 = fma2(wv[2][i], hp[i], acc2);
                acc3 = fma2(wv[3][i], hp[i], acc3);
            }
            float l0, h0v, l1, h1v, l2, h2v, l3, h3v;
            upk(acc0, l0, h0v); upk(acc1, l1, h1v);
            upk(acc2, l2, h2v); upk(acc3, l3, h3v);
            float4 v = make_float4(fsig(l0 + h0v), fsig(l1 + h1v),
                                   fsig(l2 + h2v), fsig(l3 + h3v));
            *reinterpret_cast<float4*>(op) = v;
            op += (size_t)2 * BB * OO;

            // release every 8 own-iterations (16 t): counter = t rounded up to 16
            if ((t & 15) == (14 + half) && lane == 0)
                st_release_s32(cons_a, (t | 15) + 1);
        }
        // final release covers t=TT since TT%16==0; producer cannot hang on tail
    }
}

extern "C" void kernel_launch(void* const* d_in, const int* in_sizes, int n_in,
                              void* d_out, int out_size)
{
    (void)in_sizes; (void)n_in; (void)out_size;
    const float* feed  = (const float*)d_in[0];
    const float* h0    = (const float*)d_in[1];
    const float* W_ih  = (const float*)d_in[2];
    const float* W_hh  = (const float*)d_in[3];
    const float* b_ih  = (const float*)d_in[4];
    const float* b_hh  = (const float*)d_in[5];
    const float* W_out = (const float*)d_in[6];
    const float* b_out = (const float*)d_in[7];
    float* out = (float*)d_out;

    gru_fused<<<128, 320>>>(feed, h0, W_ih, W_hh, b_ih, b_hh, W_out, b_out, out);
}

// round 15
// speedup vs baseline: 1.3095x; 1.3095x over previous
#include <cuda_runtime.h>
#include <cstdint>

#define TT 1024
#define BB 512
#define HH 15
#define II 10
#define OO 128
#define RING 32          // h-row ring depth per batch (power of 2)
#define PUB 8            // producer publishes every PUB steps
#define GUARD 16         // producer checks consumers every GUARD steps

typedef unsigned long long ull;

__device__ __forceinline__ ull pk(float lo, float hi) {
    ull r; asm("mov.b64 %0, {%1, %2};" : "=l"(r) : "f"(lo), "f"(hi)); return r;
}
__device__ __forceinline__ void upk(ull v, float& lo, float& hi) {
    asm("mov.b64 {%0, %1}, %2;" : "=f"(lo), "=f"(hi) : "l"(v));
}
__device__ __forceinline__ ull fma2(ull a, ull b, ull c) {
    ull d; asm("fma.rn.f32x2 %0, %1, %2, %3;" : "=l"(d) : "l"(a), "l"(b), "l"(c)); return d;
}
__device__ __forceinline__ ull add2(ull a, ull b) {
    ull d; asm("add.rn.f32x2 %0, %1, %2;" : "=l"(d) : "l"(a), "l"(b)); return d;
}
__device__ __forceinline__ float ftanh_mufu(float x) {
    float r; asm("tanh.approx.f32 %0, %1;" : "=f"(r) : "f"(x)); return r;
}
// Accurate sigmoid (output layer; not on the recurrence critical path)
__device__ __forceinline__ float fsig(float x) {
    float e; asm("ex2.approx.f32 %0, %1;" : "=f"(e) : "f"(-1.4426950408889634f * x));
    float d = e + 1.0f;
    float r; asm("rcp.approx.f32 %0, %1;" : "=f"(r) : "f"(d));
    return r;
}

__device__ __forceinline__ uint32_t smem_u32(const void* p) {
    uint32_t a;
    asm("{ .reg .u64 t; cvta.to.shared.u64 t, %1; cvt.u32.u64 %0, t; }" : "=r"(a) : "l"(p));
    return a;
}
__device__ __forceinline__ void sts_f32(uint32_t addr, float v) {
    asm volatile("st.shared.f32 [%0], %1;" :: "r"(addr), "f"(v) : "memory");
}
__device__ __forceinline__ void lds_v2u64(uint32_t addr, ull& a, ull& b) {
    asm volatile("ld.shared.v2.u64 {%0, %1}, [%2];" : "=l"(a), "=l"(b) : "r"(addr) : "memory");
}
__device__ __forceinline__ void st_release_s32(uint32_t addr, int v) {
    asm volatile("st.release.cta.shared.u32 [%0], %1;" :: "r"(addr), "r"(v) : "memory");
}
__device__ __forceinline__ int ld_acquire_s32(uint32_t addr) {
    int v; asm volatile("ld.acquire.cta.shared.u32 %0, [%1];" : "=r"(v) : "r"(addr) : "memory");
    return v;
}

// Rebroadcast scalar h (lane j holds h[j], j<15) into 8 packed pairs on every
// lane, pure register path (15 independent shuffles, latencies overlap).
#define BCAST(hv, hp)                                                          \
    do {                                                                       \
        _Pragma("unroll")                                                      \
        for (int _i = 0; _i < 7; _i++) {                                       \
            float _lo = __shfl_sync(0xffffffffu, (hv), 2 * _i);                \
            float _hi = __shfl_sync(0xffffffffu, (hv), 2 * _i + 1);            \
            (hp)[_i] = pk(_lo, _hi);                                           \
        }                                                                      \
        {                                                                      \
            float _lo = __shfl_sync(0xffffffffu, (hv), 14);                    \
            (hp)[7] = pk(_lo, 0.0f);                                           \
        }                                                                      \
    } while (0)

// ---------------------------------------------------------------------------
// Fused persistent kernel. Block = 12 warps (384 threads):
//   warps 8..11 : GRU recurrence producers (HIGHEST wid -> arbiter priority,
//                 one per SMSP). h rebroadcast via SHFL (register path);
//                 STS ring publish is fire-and-forget off the critical path;
//                 syncwarp+release amortized once per PUB chunk.
//   warps 0..7  : output projection consumers, TWO per batch, parity-split
//                 over t (half=0 even t, half=1 odd t)
// ---------------------------------------------------------------------------
__global__ void __launch_bounds__(384, 1) gru_fused(
    const float* __restrict__ feed, const float* __restrict__ h0,
    const float* __restrict__ W_ih, const float* __restrict__ W_hh,
    const float* __restrict__ b_ih, const float* __restrict__ b_hh,
    const float* __restrict__ W_out, const float* __restrict__ b_out,
    float* __restrict__ out)
{
    __shared__ __align__(16) float hring[4][RING][16];   // 8 KB
    __shared__ int prod[4];
    __shared__ int cons[4][2];

    const int tid  = threadIdx.x;
    const int wid  = tid >> 5;
    const int lane = tid & 31;

    // zero ring (column 15 of every slot must stay 0 forever for consumer
    // vector loads) + counters
    for (int i = tid; i < 4 * RING * 16; i += 384)
        (&hring[0][0][0])[i] = 0.0f;
    if (tid < 4) prod[tid] = 0;
    if (tid < 8) cons[tid >> 1][tid & 1] = 0;
    __syncthreads();

    if (wid >= 8) {
        // ================= producer: recurrence =================
        const int bl = wid - 8;
        const int b  = blockIdx.x * 4 + bl;
        const uint32_t ring_a  = smem_u32(&hring[bl][0][0]);
        const uint32_t prod_a  = smem_u32(&prod[bl]);
        const uint32_t cons_a0 = smem_u32(&cons[bl][0]);
        const uint32_t cons_a1 = smem_u32(&cons[bl][1]);

        const int j = (lane < HH) ? lane : 0;       // inactive lanes shadow unit 0

        // W_hh rows j (r), 15+j (z) scaled by 0.5 ; 30+j (n) unscaled
        ull wr[8], wz[8], wn[8];
#pragma unroll
        for (int i = 0; i < 8; i++) {
            const int k0 = 2 * i, k1 = 2 * i + 1;
            float r0 = W_hh[j * HH + k0]            * 0.5f;
            float z0 = W_hh[(HH + j) * HH + k0]     * 0.5f;
            float n0 = W_hh[(2 * HH + j) * HH + k0];
            float r1 = (k1 < HH) ? W_hh[j * HH + k1]            * 0.5f : 0.0f;
            float z1 = (k1 < HH) ? W_hh[(HH + j) * HH + k1]     * 0.5f : 0.0f;
            float n1 = (k1 < HH) ? W_hh[(2 * HH + j) * HH + k1]        : 0.0f;
            wr[i] = pk(r0, r1); wz[i] = pk(z0, z1); wn[i] = pk(n0, n1);
        }

        float cr = b_ih[j]          + b_hh[j];
        float cz = b_ih[HH + j]     + b_hh[HH + j];
        float cn = b_ih[2 * HH + j];
        float bn = b_hh[2 * HH + j];
#pragma unroll
        for (int k = 0; k < II; k++) {
            float xk = feed[b * II + k];
            cr = fmaf(xk, W_ih[j * II + k],            cr);
            cz = fmaf(xk, W_ih[(HH + j) * II + k],     cz);
            cn = fmaf(xk, W_ih[(2 * HH + j) * II + k], cn);
        }
        cr *= 0.5f;
        cz *= 0.5f;

        float h = (lane < HH) ? h0[b * HH + j] : 0.0f;

        const ull crp = pk(cr, 0.0f);
        const ull czp = pk(cz, 0.0f);
        const ull bnp = pk(bn, 0.0f);

        // prime hp purely in registers
        ull hp[8];
        BCAST(h, hp);

        for (int t0 = 0; t0 < TT; t0 += PUB) {
            // overrun guard at chunk boundary (every GUARD steps):
            // need all t < t0-16 consumed by BOTH parity consumers
            if ((t0 & (GUARD - 1)) == 0) {
                for (;;) {
                    int c0 = ld_acquire_s32(cons_a0);
                    int c1 = ld_acquire_s32(cons_a1);
                    int cm = c0 < c1 ? c0 : c1;
                    if (t0 - cm <= (RING - GUARD)) break;
                    __nanosleep(32);
                }
            }
#pragma unroll
            for (int tt = 0; tt < PUB; tt++) {
                const int t = t0 + tt;
                // gate dots: 6 independent f32x2 chains
                ull ar0 = crp, az0 = czp, an0 = bnp;
                ull ar1 = 0ULL, az1 = 0ULL, an1 = 0ULL;
#pragma unroll
                for (int i = 0; i < 4; i++) {
                    ar0 = fma2(wr[i], hp[i], ar0);
                    az0 = fma2(wz[i], hp[i], az0);
                    an0 = fma2(wn[i], hp[i], an0);
                }
#pragma unroll
                for (int i = 4; i < 8; i++) {
                    ar1 = fma2(wr[i], hp[i], ar1);
                    az1 = fma2(wz[i], hp[i], az1);
                    an1 = fma2(wn[i], hp[i], an1);
                }
                float rl, rh, zl, zh, nl, nh;
                upk(add2(ar0, ar1), rl, rh);
                upk(add2(az0, az1), zl, zh);
                upk(add2(an0, an1), nl, nh);
                const float gr = rl + rh;     // (r preact) * 0.5
                const float gz = zl + zh;     // (z preact) * 0.5
                const float gn = nl + nh;     // h-dot + b_hh_n

                // r*gn + cn == 0.5*gn*tr + (0.5*gn + cn); pn,qn compute in the
                // shadow of tanh(gr) so n's argument is ready 4cyc after tr.
                const float tr  = ftanh_mufu(gr);
                const float tz  = ftanh_mufu(gz);
                const float pn  = 0.5f * gn;
                const float qn  = pn + cn;
                const float omz = fmaf(-0.5f, tz, 0.5f);      // 1 - z
                const float zh2 = fmaf(0.5f, tz, 0.5f) * h;   // z*h, off n-path
                const float n   = ftanh_mufu(fmaf(pn, tr, qn));
                h = fmaf(omz, n, zh2);

                // publish for consumers: fire-and-forget, off critical path
                const uint32_t sa = ring_a + (uint32_t)((t & (RING - 1)) * 64);
                if (lane < HH) sts_f32(sa + (uint32_t)lane * 4, h);

                // rebroadcast via registers (critical path: h -> shfl -> hp)
                BCAST(h, hp);
            }
            // amortized ordering + release: one syncwarp per chunk orders all
            // lanes' STS of the whole chunk before lane0's release store.
            __syncwarp();
            if (lane == 0) st_release_s32(prod_a, t0 + PUB);
        }
    } else {
        // ================= consumer: output projection =================
        // two warps per batch, parity-split over t
        const int bl   = wid & 3;
        const int half = wid >> 2;                 // 0: even t, 1: odd t
        const int b    = blockIdx.x * 4 + bl;
        const uint32_t ring_a = smem_u32(&hring[bl][0][0]);
        const uint32_t prod_a = smem_u32(&prod[bl]);
        const uint32_t cons_a = smem_u32(&cons[bl][half]);

        const int o0 = lane * 4;
        ull wv[4][8];
        ull bo2[4];
#pragma unroll
        for (int oo = 0; oo < 4; oo++) {
            bo2[oo] = pk(b_out[o0 + oo], 0.0f);
#pragma unroll
            for (int i = 0; i < 8; i++) {
                const int k0 = 2 * i, k1 = 2 * i + 1;
                float w0 = W_out[(o0 + oo) * HH + k0];
                float w1 = (k1 < HH) ? W_out[(o0 + oo) * HH + k1] : 0.0f;
                wv[oo][i] = pk(w0, w1);
            }
        }

        float* op = out + (size_t)(half) * BB * OO + (size_t)b * OO + o0;

        for (int t = half; t < TT; t += 2) {
            // throttled spin; producer publishes in chunks of PUB
            while (ld_acquire_s32(prod_a) <= t) { __nanosleep(32); }

            uint32_t sa = ring_a + (uint32_t)((t & (RING - 1)) * 64);
            ull hp[8];
            lds_v2u64(sa,      hp[0], hp[1]);
            lds_v2u64(sa + 16, hp[2], hp[3]);
            lds_v2u64(sa + 32, hp[4], hp[5]);
            lds_v2u64(sa + 48, hp[6], hp[7]);

            ull acc0 = bo2[0], acc1 = bo2[1], acc2 = bo2[2], acc3 = bo2[3];
#pragma unroll
            for (int i = 0; i < 8; i++) {       // 4 independent chains
                acc0 = fma2(wv[0][i], hp[i], acc0);
                acc1 = fma2(wv[1][i], hp[i], acc1);
                acc2 = fma2(wv[2][i], hp[i], acc2);
                acc3 = fma2(wv[3][i], hp[i], acc3);
            }
            float l0, h0v, l1, h1v, l2, h2v, l3, h3v;
            upk(acc0, l0, h0v); upk(acc1, l1, h1v);
            upk(acc2, l2, h2v); upk(acc3, l3, h3v);
            float4 v = make_float4(fsig(l0 + h0v), fsig(l1 + h1v),
                                   fsig(l2 + h2v), fsig(l3 + h3v));
            *reinterpret_cast<float4*>(op) = v;
            op += (size_t)2 * BB * OO;

            // release every 8 own-iterations (16 t): counter = t rounded up to 16
            if ((t & 15) == (14 + half) && lane == 0)
                st_release_s32(cons_a, (t | 15) + 1);
        }
        // final release covers t=TT since TT%16==0; producer cannot hang on tail
    }
}

extern "C" void kernel_launch(void* const* d_in, const int* in_sizes, int n_in,
                              void* d_out, int out_size)
{
    (void)in_sizes; (void)n_in; (void)out_size;
    const float* feed  = (const float*)d_in[0];
    const float* h0    = (const float*)d_in[1];
    const float* W_ih  = (const float*)d_in[2];
    const float* W_hh  = (const float*)d_in[3];
    const float* b_ih  = (const float*)d_in[4];
    const float* b_hh  = (const float*)d_in[5];
    const float* W_out = (const float*)d_in[6];
    const float* b_out = (const float*)d_in[7];
    float* out = (float*)d_out;

    gru_fused<<<128, 384>>>(feed, h0, W_ih, W_hh, b_ih, b_hh, W_out, b_out, out);
}

// round 17
// speedup vs baseline: 1.3835x; 1.0565x over previous
#include <cuda_runtime.h>
#include <cstdint>

#define TT 1024
#define BB 512
#define HH 15
#define II 10
#define OO 128
#define RING 32          // h-row ring depth per batch (power of 2)
#define PUB 8            // producer publishes/releases every PUB steps
#define GUARD 16         // producer checks consumers every GUARD steps

typedef unsigned long long ull;

__device__ __forceinline__ ull pk(float lo, float hi) {
    ull r; asm("mov.b64 %0, {%1, %2};" : "=l"(r) : "f"(lo), "f"(hi)); return r;
}
__device__ __forceinline__ void upk(ull v, float& lo, float& hi) {
    asm("mov.b64 {%0, %1}, %2;" : "=f"(lo), "=f"(hi) : "l"(v));
}
__device__ __forceinline__ ull fma2(ull a, ull b, ull c) {
    ull d; asm("fma.rn.f32x2 %0, %1, %2, %3;" : "=l"(d) : "l"(a), "l"(b), "l"(c)); return d;
}
__device__ __forceinline__ ull add2(ull a, ull b) {
    ull d; asm("add.rn.f32x2 %0, %1, %2;" : "=l"(d) : "l"(a), "l"(b)); return d;
}
__device__ __forceinline__ float ftanh_mufu(float x) {
    float r; asm("tanh.approx.f32 %0, %1;" : "=f"(r) : "f"(x)); return r;
}
// Accurate sigmoid (output layer; not on the recurrence critical path)
__device__ __forceinline__ float fsig(float x) {
    float e; asm("ex2.approx.f32 %0, %1;" : "=f"(e) : "f"(-1.4426950408889634f * x));
    float d = e + 1.0f;
    float r; asm("rcp.approx.f32 %0, %1;" : "=f"(r) : "f"(d));
    return r;
}

__device__ __forceinline__ uint32_t smem_u32(const void* p) {
    uint32_t a;
    asm("{ .reg .u64 t; cvta.to.shared.u64 t, %1; cvt.u32.u64 %0, t; }" : "=r"(a) : "l"(p));
    return a;
}
__device__ __forceinline__ void sts_f32(uint32_t addr, float v) {
    asm volatile("st.shared.f32 [%0], %1;" :: "r"(addr), "f"(v) : "memory");
}
__device__ __forceinline__ void lds_v2u64(uint32_t addr, ull& a, ull& b) {
    asm volatile("ld.shared.v2.u64 {%0, %1}, [%2];" : "=l"(a), "=l"(b) : "r"(addr) : "memory");
}
__device__ __forceinline__ void st_release_s32(uint32_t addr, int v) {
    asm volatile("st.release.cta.shared.u32 [%0], %1;" :: "r"(addr), "r"(v) : "memory");
}
__device__ __forceinline__ int ld_acquire_s32(uint32_t addr) {
    int v; asm volatile("ld.acquire.cta.shared.u32 %0, [%1];" : "=r"(v) : "r"(addr) : "memory");
    return v;
}

// ---------------------------------------------------------------------------
// Fused persistent kernel. Block = 12 warps (384 threads):
//   warps 8..11 : GRU recurrence producers (HIGHEST wid -> arbiter priority,
//                 one per SMSP). Publish-reload via STS/syncwarp/LDS (proven
//                 faster than SHFL broadcast in R15 A/B).
//   warps 0..7  : output projection consumers, TWO per batch, parity-split
//                 over t. prod counter CACHED in a register to strip
//                 acquire traffic off the shared MIO/LSU port.
// ---------------------------------------------------------------------------
__global__ void __launch_bounds__(384, 1) gru_fused(
    const float* __restrict__ feed, const float* __restrict__ h0,
    const float* __restrict__ W_ih, const float* __restrict__ W_hh,
    const float* __restrict__ b_ih, const float* __restrict__ b_hh,
    const float* __restrict__ W_out, const float* __restrict__ b_out,
    float* __restrict__ out)
{
    __shared__ __align__(16) float hring[4][RING][16];   // 8 KB
    __shared__ int prod[4];
    __shared__ int cons[4][2];

    const int tid  = threadIdx.x;
    const int wid  = tid >> 5;
    const int lane = tid & 31;

    // zero ring (column 15 of every slot must stay 0 forever) + counters
    for (int i = tid; i < 4 * RING * 16; i += 384)
        (&hring[0][0][0])[i] = 0.0f;
    if (tid < 4) prod[tid] = 0;
    if (tid < 8) cons[tid >> 1][tid & 1] = 0;
    __syncthreads();

    if (wid >= 8) {
        // ================= producer: recurrence =================
        const int bl = wid - 8;
        const int b  = blockIdx.x * 4 + bl;
        const uint32_t ring_a  = smem_u32(&hring[bl][0][0]);
        const uint32_t prod_a  = smem_u32(&prod[bl]);
        const uint32_t cons_a0 = smem_u32(&cons[bl][0]);
        const uint32_t cons_a1 = smem_u32(&cons[bl][1]);

        const int j = (lane < HH) ? lane : 0;       // inactive lanes shadow unit 0

        // W_hh rows j (r), 15+j (z) scaled by 0.5 ; 30+j (n) unscaled
        ull wr[8], wz[8], wn[8];
#pragma unroll
        for (int i = 0; i < 8; i++) {
            const int k0 = 2 * i, k1 = 2 * i + 1;
            float r0 = W_hh[j * HH + k0]            * 0.5f;
            float z0 = W_hh[(HH + j) * HH + k0]     * 0.5f;
            float n0 = W_hh[(2 * HH + j) * HH + k0];
            float r1 = (k1 < HH) ? W_hh[j * HH + k1]            * 0.5f : 0.0f;
            float z1 = (k1 < HH) ? W_hh[(HH + j) * HH + k1]     * 0.5f : 0.0f;
            float n1 = (k1 < HH) ? W_hh[(2 * HH + j) * HH + k1]        : 0.0f;
            wr[i] = pk(r0, r1); wz[i] = pk(z0, z1); wn[i] = pk(n0, n1);
        }

        float cr = b_ih[j]          + b_hh[j];
        float cz = b_ih[HH + j]     + b_hh[HH + j];
        float cn = b_ih[2 * HH + j];
        float bn = b_hh[2 * HH + j];
#pragma unroll
        for (int k = 0; k < II; k++) {
            float xk = feed[b * II + k];
            cr = fmaf(xk, W_ih[j * II + k],            cr);
            cz = fmaf(xk, W_ih[(HH + j) * II + k],     cz);
            cn = fmaf(xk, W_ih[(2 * HH + j) * II + k], cn);
        }
        cr *= 0.5f;
        cz *= 0.5f;

        float h = (lane < HH) ? h0[b * HH + j] : 0.0f;

        const ull crp = pk(cr, 0.0f);
        const ull czp = pk(cz, 0.0f);
        const ull bnp = pk(bn, 0.0f);

        // prime: publish initial h into scratch slot RING-1, reload packed.
        // Safe: consumers cannot touch slot RING-1 until prod >= RING, and the
        // producer rewrites it with real data at t = RING-1.
        {
            uint32_t sa = ring_a + (uint32_t)((RING - 1) * 64);
            if (lane < HH) sts_f32(sa + (uint32_t)lane * 4, h);
            __syncwarp();
        }
        ull hp[8];
        {
            uint32_t sa = ring_a + (uint32_t)((RING - 1) * 64);
            lds_v2u64(sa,      hp[0], hp[1]);
            lds_v2u64(sa + 16, hp[2], hp[3]);
            lds_v2u64(sa + 32, hp[4], hp[5]);
            lds_v2u64(sa + 48, hp[6], hp[7]);
        }

        for (int t0 = 0; t0 < TT; t0 += PUB) {
            // overrun guard at chunk boundary (every GUARD steps):
            // need all t < t0-16 consumed by BOTH parity consumers
            if ((t0 & (GUARD - 1)) == 0) {
                for (;;) {
                    int c0 = ld_acquire_s32(cons_a0);
                    int c1 = ld_acquire_s32(cons_a1);
                    int cm = c0 < c1 ? c0 : c1;
                    if (t0 - cm <= (RING - GUARD)) break;
                    __nanosleep(32);
                }
            }
#pragma unroll
            for (int tt = 0; tt < PUB; tt++) {
                const int t = t0 + tt;
                // gate dots: 6 independent f32x2 chains
                ull ar0 = crp, az0 = czp, an0 = bnp;
                ull ar1 = 0ULL, az1 = 0ULL, an1 = 0ULL;
#pragma unroll
                for (int i = 0; i < 4; i++) {
                    ar0 = fma2(wr[i], hp[i], ar0);
                    az0 = fma2(wz[i], hp[i], az0);
                    an0 = fma2(wn[i], hp[i], an0);
                }
#pragma unroll
                for (int i = 4; i < 8; i++) {
                    ar1 = fma2(wr[i], hp[i], ar1);
                    az1 = fma2(wz[i], hp[i], az1);
                    an1 = fma2(wn[i], hp[i], an1);
                }
                float rl, rh, zl, zh, nl, nh;
                upk(add2(ar0, ar1), rl, rh);
                upk(add2(az0, az1), zl, zh);
                upk(add2(an0, an1), nl, nh);
                const float gr = rl + rh;     // (r preact) * 0.5
                const float gz = zl + zh;     // (z preact) * 0.5
                const float gn = nl + nh;     // h-dot + b_hh_n

                // r*gn + cn == 0.5*gn*tr + (0.5*gn + cn); pn,qn compute in the
                // shadow of tanh(gr) so n's argument is ready 4cyc after tr.
                const float tr  = ftanh_mufu(gr);
                const float tz  = ftanh_mufu(gz);
                const float pn  = 0.5f * gn;
                const float qn  = pn + cn;
                const float omz = fmaf(-0.5f, tz, 0.5f);      // 1 - z
                const float zh2 = fmaf(0.5f, tz, 0.5f) * h;   // z*h, off n-path
                const float n   = ftanh_mufu(fmaf(pn, tr, qn));
                h = fmaf(omz, n, zh2);

                // publish h scalars -> ring slot; syncwarp; reload packed.
                // (Proven faster than SHFL broadcast — R13 vs R15 A/B.)
                const uint32_t sa = ring_a + (uint32_t)((t & (RING - 1)) * 64);
                if (lane < HH) sts_f32(sa + (uint32_t)lane * 4, h);
                __syncwarp();
                lds_v2u64(sa,      hp[0], hp[1]);
                lds_v2u64(sa + 16, hp[2], hp[3]);
                lds_v2u64(sa + 32, hp[4], hp[5]);
                lds_v2u64(sa + 48, hp[6], hp[7]);
            }
            // amortized release: the last step's syncwarp already ordered all
            // lanes' STS of the whole chunk before this release store.
            if (lane == 0) st_release_s32(prod_a, t0 + PUB);
        }
    } else {
        // ================= consumer: output projection =================
        // two warps per batch, parity-split over t; prod counter cached in a
        // register so the acquire load leaves the MIO port mostly idle.
        const int bl   = wid & 3;
        const int half = wid >> 2;                 // 0: even t, 1: odd t
        const int b    = blockIdx.x * 4 + bl;
        const uint32_t ring_a = smem_u32(&hring[bl][0][0]);
        const uint32_t prod_a = smem_u32(&prod[bl]);
        const uint32_t cons_a = smem_u32(&cons[bl][half]);

        const int o0 = lane * 4;
        ull wv[4][8];
        ull bo2[4];
#pragma unroll
        for (int oo = 0; oo < 4; oo++) {
            bo2[oo] = pk(b_out[o0 + oo], 0.0f);
#pragma unroll
            for (int i = 0; i < 8; i++) {
                const int k0 = 2 * i, k1 = 2 * i + 1;
                float w0 = W_out[(o0 + oo) * HH + k0];
                float w1 = (k1 < HH) ? W_out[(o0 + oo) * HH + k1] : 0.0f;
                wv[oo][i] = pk(w0, w1);
            }
        }

        float* op = out + (size_t)(half) * BB * OO + (size_t)b * OO + o0;

        int P = 0;                                  // cached prod counter
        for (int t = half; t < TT; t += 2) {
            if (P <= t) {
                // acquire once; ordering persists for all slots < P
                for (;;) {
                    P = ld_acquire_s32(prod_a);
                    if (P > t) break;
                    __nanosleep(32);
                }
            }

            uint32_t sa = ring_a + (uint32_t)((t & (RING - 1)) * 64);
            ull hp[8];
            lds_v2u64(sa,      hp[0], hp[1]);
            lds_v2u64(sa + 16, hp[2], hp[3]);
            lds_v2u64(sa + 32, hp[4], hp[5]);
            lds_v2u64(sa + 48, hp[6], hp[7]);

            ull acc0 = bo2[0], acc1 = bo2[1], acc2 = bo2[2], acc3 = bo2[3];
#pragma unroll
            for (int i = 0; i < 8; i++) {       // 4 independent chains
                acc0 = fma2(wv[0][i], hp[i], acc0);
                acc1 = fma2(wv[1][i], hp[i], acc1);
                acc2 = fma2(wv[2][i], hp[i], acc2);
                acc3 = fma2(wv[3][i], hp[i], acc3);
            }
            float l0, h0v, l1, h1v, l2, h2v, l3, h3v;
            upk(acc0, l0, h0v); upk(acc1, l1, h1v);
            upk(acc2, l2, h2v); upk(acc3, l3, h3v);
            float4 v = make_float4(fsig(l0 + h0v), fsig(l1 + h1v),
                                   fsig(l2 + h2v), fsig(l3 + h3v));
            *reinterpret_cast<float4*>(op) = v;
            op += (size_t)2 * BB * OO;

            // release every 8 own-iterations (16 t): counter = t rounded up to 16
            if ((t & 15) == (14 + half) && lane == 0)
                st_release_s32(cons_a, (t | 15) + 1);
        }
        // final release covers t=TT since TT%16==0; producer cannot hang on tail
    }
}

extern "C" void kernel_launch(void* const* d_in, const int* in_sizes, int n_in,
                              void* d_out, int out_size)
{
    (void)in_sizes; (void)n_in; (void)out_size;
    const float* feed  = (const float*)d_in[0];
    const float* h0    = (const float*)d_in[1];
    const float* W_ih  = (const float*)d_in[2];
    const float* W_hh  = (const float*)d_in[3];
    const float* b_ih  = (const float*)d_in[4];
    const float* b_hh  = (const float*)d_in[5];
    const float* W_out = (const float*)d_in[6];
    const float* b_out = (const float*)d_in[7];
    float* out = (float*)d_out;

    gru_fused<<<128, 384>>>(feed, h0, W_ih, W_hh, b_ih, b_hh, W_out, b_out, out);
}